// round 14
// baseline (speedup 1.0000x reference)
#include <cuda_runtime.h>
#include <cuda_bf16.h>
#include <cstdint>

#define KTAGS 11
#define TT    2048
#define BB    4096
#define CH    8              // steps per chunk
#define NCHK  (TT / CH)      // 256
#define DEPTH 4
#define WARPS_PB 3
#define SEQ_PW   10
#define SEQ_PB   (WARPS_PB * SEQ_PW)   // 30
#define THREADS  (WARPS_PB * 32)       // 96
#define FSTRIDE  92
#define START_TAG 10
#define STOP_TAG  9
#define EX2C 1.4426950408889634f   // log2(e)

__device__ __forceinline__ float ex2f(float x) {
    float r; asm("ex2.approx.f32 %0, %1;" : "=f"(r) : "f"(x)); return r;
}
__device__ __forceinline__ void kfold(float x, float& s, float& c) {
    float y = x - c;
    float t = s + y;
    c = (t - s) - y;
    s = t;
}

// One gold-shifted forward step on PRELOADED operands (no memory on the chain).
template<bool DONORM>
__device__ __forceinline__ void crf_step_r(float f0, float f1, float f2, float ndc,
                                           const float (&E)[3][9],
                                           int peer1, int peer2,
                                           float& a0, float& a1, float& a2,
                                           float& LS, float& LC)
{
    float b0 = __shfl_sync(0xffffffffu, a0, peer1);
    float b1 = __shfl_sync(0xffffffffu, a1, peer1);
    float b2 = __shfl_sync(0xffffffffu, a2, peer1);
    float c0 = __shfl_sync(0xffffffffu, a0, peer2);
    float c1 = __shfl_sync(0xffffffffu, a1, peer2);
    float c2 = __shfl_sync(0xffffffffu, a2, peer2);

    float s0 = E[0][0] * a0;
    s0 = fmaf(E[0][1], a1, s0); s0 = fmaf(E[0][2], a2, s0);
    s0 = fmaf(E[0][3], b0, s0); s0 = fmaf(E[0][4], b1, s0); s0 = fmaf(E[0][5], b2, s0);
    s0 = fmaf(E[0][6], c0, s0); s0 = fmaf(E[0][7], c1, s0); s0 = fmaf(E[0][8], c2, s0);
    float s1 = E[1][0] * a0;
    s1 = fmaf(E[1][1], a1, s1); s1 = fmaf(E[1][2], a2, s1);
    s1 = fmaf(E[1][3], b0, s1); s1 = fmaf(E[1][4], b1, s1); s1 = fmaf(E[1][5], b2, s1);
    s1 = fmaf(E[1][6], c0, s1); s1 = fmaf(E[1][7], c1, s1); s1 = fmaf(E[1][8], c2, s1);
    float s2 = E[2][0] * a0;
    s2 = fmaf(E[2][1], a1, s2); s2 = fmaf(E[2][2], a2, s2);
    s2 = fmaf(E[2][3], b0, s2); s2 = fmaf(E[2][4], b1, s2); s2 = fmaf(E[2][5], b2, s2);
    s2 = fmaf(E[2][6], c0, s2); s2 = fmaf(E[2][7], c1, s2); s2 = fmaf(E[2][8], c2, s2);

    if (DONORM) {
        float m = fmaxf(a0, a1); m = fmaxf(m, a2);
        m = fmaxf(m, b0); m = fmaxf(m, b1); m = fmaxf(m, b2);
        m = fmaxf(m, c0); m = fmaxf(m, c1); m = fmaxf(m, c2);
        float lm = __logf(m);
        kfold(lm, LS, LC);
        ndc = fmaf(-lm, EX2C, ndc);
    }
    a0 = ex2f(fmaf(f0, EX2C, ndc)) * s0;
    a1 = ex2f(fmaf(f1, EX2C, ndc)) * s1;
    a2 = ex2f(fmaf(f2, EX2C, ndc)) * s2;
}

__global__ void __launch_bounds__(THREADS, 1)
crf_nll_kernel(const float* __restrict__ feats,
               const int*   __restrict__ tags,
               const float* __restrict__ trans,
               float* __restrict__ out)
{
    __shared__ __align__(16) float s_feats[DEPTH][WARPS_PB][SEQ_PW][FSTRIDE]; // 44160 B
    __shared__ __align__(16) int   s_tags [DEPTH][WARPS_PB][SEQ_PW][CH];      //  3840 B
    __shared__ float s_trans[KTAGS * KTAGS];

    const int tid = threadIdx.x;
    if (tid < KTAGS * KTAGS) s_trans[tid] = trans[tid];
    __syncthreads();

    const int w    = tid >> 5;
    const int lane = tid & 31;
    int grp, k;
    if (lane < 30) { grp = lane / 3; k = lane - 3 * grp; }
    else           { grp = 0;        k = lane - 30;      }
    const int glane = 3 * grp;
    const int k1 = (k + 1) % 3, k2 = (k + 2) % 3;
    const int peer1 = glane + k1, peer2 = glane + k2;
    const int row0 = 3 * k;
    const int b = blockIdx.x * SEQ_PB + w * SEQ_PW + grp;
    const bool writer = (lane < 30) && (k == 0) && (b < BB);

    float E[3][9], SV[3], ES[3];
#pragma unroll
    for (int i = 0; i < 3; i++) {
        const float* tr = &s_trans[(row0 + i) * KTAGS];
#pragma unroll
        for (int q = 0; q < 3; q++) {
            E[i][q]     = __expf(tr[3 * k  + q]);
            E[i][3 + q] = __expf(tr[3 * k1 + q]);
            E[i][6 + q] = __expf(tr[3 * k2 + q]);
        }
        SV[i] = tr[START_TAG];
        ES[i] = __expf(s_trans[STOP_TAG * KTAGS + (row0 + i)]);
    }

    // ---- cp.async plan (proven): 240 16B units spread over all 32 lanes ----
    const char* srcp[8];
    uint32_t    dstp[8];
    int         sadv[8];
    int         dadv[8];
    bool        act [8];
#pragma unroll
    for (int r = 0; r < 8; r++) {
        int u = lane + 32 * r;
        act[r] = (u < 240);
        int uu = act[r] ? u : 0;
        int s  = uu / 24;
        int kk = uu % 24;
        int bs = blockIdx.x * SEQ_PB + w * SEQ_PW + s;
        if (bs >= BB) bs = BB - 1;
        if (kk < 22) {
            srcp[r] = (const char*)feats + (size_t)bs * TT * KTAGS * 4 + kk * 16;
            sadv[r] = CH * KTAGS * 4;
            dstp[r] = (uint32_t)__cvta_generic_to_shared(&s_feats[0][w][s][kk * 4]);
            dadv[r] = (int)sizeof(s_feats[0]);
        } else {
            srcp[r] = (const char*)tags + (size_t)bs * TT * 4 + (kk - 22) * 16;
            sadv[r] = CH * 4;
            dstp[r] = (uint32_t)__cvta_generic_to_shared(&s_tags[0][w][s][(kk - 22) * 4]);
            dadv[r] = (int)sizeof(s_tags[0]);
        }
    }

    auto issue_chunk = [&](int c) {
        int d = c & (DEPTH - 1);
#pragma unroll
        for (int r = 0; r < 8; r++) {
            if (act[r]) {
                uint32_t dd = dstp[r] + d * dadv[r];
                const char* ss = srcp[r] + (size_t)c * sadv[r];
                asm volatile("cp.async.ca.shared.global [%0], [%1], 16;" :: "r"(dd), "l"(ss));
            }
        }
        asm volatile("cp.async.commit_group;" ::: "memory");
    };

#pragma unroll
    for (int c = 0; c < DEPTH; c++) issue_chunk(c);

    float a0 = 0.f, a1 = 0.f, a2 = 0.f;
    float LS = 0.f, LC = 0.f;
    int   tagprev = START_TAG;

    // One 8-step slot: batched preload (full MLP), then pure-register steps.
    auto do8 = [&](int d, bool c0peel) {
        const float* sf = &s_feats[d][w][grp][0];
        const int4*  tq = (const int4*)&s_tags[d][w][grp][0];
        int4 tA = tq[0], tB = tq[1];
        int tgs[8] = {tA.x, tA.y, tA.z, tA.w, tB.x, tB.y, tB.z, tB.w};

        float F0[CH], F1[CH], F2[CH], NDC[CH];
        int tprev = tagprev;
#pragma unroll
        for (int t = 0; t < CH; t++) {
            const float* fr = &sf[t * KTAGS + row0];
            F0[t] = fr[0]; F1[t] = fr[1]; F2[t] = fr[2];
            float fg  = sf[t * KTAGS + tgs[t]];
            float trg = s_trans[tgs[t] * KTAGS + tprev];
            NDC[t] = (-fg - trg) * EX2C;
            tprev = tgs[t];
        }
        tagprev = tprev;

        if (c0peel) {
            // t = 0: a_j = ex2((SV_j + f_j)*C + NDC[0])   (prev=START only)
            a0 = ex2f(fmaf(SV[0] + F0[0], EX2C, NDC[0]));
            a1 = ex2f(fmaf(SV[1] + F1[0], EX2C, NDC[0]));
            a2 = ex2f(fmaf(SV[2] + F2[0], EX2C, NDC[0]));
        } else {
            crf_step_r<true>(F0[0], F1[0], F2[0], NDC[0], E, peer1, peer2,
                             a0, a1, a2, LS, LC);
        }
#pragma unroll
        for (int t = 1; t < CH; t++)
            crf_step_r<false>(F0[t], F1[t], F2[t], NDC[t], E, peer1, peer2,
                              a0, a1, a2, LS, LC);
    };

    // Paired-chunk loop: one wait + one sync pair per 16 steps.
    for (int c = 0; c < NCHK; c += 2) {
        asm volatile("cp.async.wait_group %0;" :: "n"(DEPTH - 2) : "memory");
        __syncwarp();

        do8(c & (DEPTH - 1), c == 0);
        do8((c + 1) & (DEPTH - 1), false);

        __syncwarp();
        if (c + DEPTH < NCHK) {
            issue_chunk(c + DEPTH);
            issue_chunk(c + DEPTH + 1);
        } else {
            asm volatile("cp.async.commit_group;" ::: "memory");
            asm volatile("cp.async.commit_group;" ::: "memory");
        }
    }

    // finalize: NLL = L + log( sum_p a_p * exp(trans[STOP,p]) ) - trans[STOP, tag_last]
    float term = a0 * ES[0];
    term = fmaf(a1, ES[1], term);
    term = fmaf(a2, ES[2], term);
    float fsum = term + __shfl_sync(0xffffffffu, term, peer1)
                      + __shfl_sync(0xffffffffu, term, peer2);

    float res = (LS - LC) + __logf(fsum) - s_trans[STOP_TAG * KTAGS + tagprev];

    if (writer) out[b] = res;
}

extern "C" void kernel_launch(void* const* d_in, const int* in_sizes, int n_in,
                              void* d_out, int out_size)
{
    const float* feats = (const float*)d_in[0];
    const int*   tags  = (const int*)d_in[1];
    const float* trans = (const float*)d_in[2];
    float* out = (float*)d_out;

    dim3 grid((BB + SEQ_PB - 1) / SEQ_PB);   // 137 blocks, single wave
    dim3 block(THREADS);                     // 96 threads = 3 warps = 30 sequences
    crf_nll_kernel<<<grid, block>>>(feats, tags, trans, out);
}

// round 15
// speedup vs baseline: 1.6543x; 1.6543x over previous
#include <cuda_runtime.h>
#include <cuda_bf16.h>
#include <cstdint>

#define KTAGS 11
#define TT    2048
#define BB    4096
#define CH    8              // steps per chunk
#define NCHK  (TT / CH)      // 256
#define DEPTH 4
#define WARPS_PB 3
#define SEQ_PW   10
#define SEQ_PB   (WARPS_PB * SEQ_PW)   // 30
#define THREADS  (WARPS_PB * 32)       // 96
#define FSTRIDE  92
#define START_TAG 10
#define STOP_TAG  9
#define EX2C 1.4426950408889634f   // log2(e)

__device__ __forceinline__ float ex2f(float x) {
    float r; asm("ex2.approx.f32 %0, %1;" : "=f"(r) : "f"(x)); return r;
}
__device__ __forceinline__ void kfold(float x, float& s, float& c) {
    float y = x - c;
    float t = s + y;
    c = (t - s) - y;
    s = t;
}

// One gold-shifted forward step. Single-chain dots, own states first
// (head of chain overlaps the shuffle latency). In-step LDS left to ptxas
// to schedule (R13 proved manual hoisting tips it into local memory).
template<bool DONORM>
__device__ __forceinline__ void crf_step(const float* __restrict__ sf, int tc, int tg,
                                         const float* __restrict__ s_trans,
                                         const float (&E)[3][9],
                                         int peer1, int peer2, int row0,
                                         float& a0, float& a1, float& a2,
                                         float& LS, float& LC, int& tagprev)
{
    const float* fr = &sf[tc * KTAGS + row0];
    float f0 = fr[0], f1 = fr[1], f2 = fr[2];
    float fg  = sf[tc * KTAGS + tg];              // group-uniform smem broadcast
    float trg = s_trans[tg * KTAGS + tagprev];    // group-uniform

    float b0 = __shfl_sync(0xffffffffu, a0, peer1);
    float b1 = __shfl_sync(0xffffffffu, a1, peer1);
    float b2 = __shfl_sync(0xffffffffu, a2, peer1);
    float c0 = __shfl_sync(0xffffffffu, a0, peer2);
    float c1 = __shfl_sync(0xffffffffu, a1, peer2);
    float c2 = __shfl_sync(0xffffffffu, a2, peer2);

    float s0 = E[0][0] * a0;
    s0 = fmaf(E[0][1], a1, s0); s0 = fmaf(E[0][2], a2, s0);
    s0 = fmaf(E[0][3], b0, s0); s0 = fmaf(E[0][4], b1, s0); s0 = fmaf(E[0][5], b2, s0);
    s0 = fmaf(E[0][6], c0, s0); s0 = fmaf(E[0][7], c1, s0); s0 = fmaf(E[0][8], c2, s0);
    float s1 = E[1][0] * a0;
    s1 = fmaf(E[1][1], a1, s1); s1 = fmaf(E[1][2], a2, s1);
    s1 = fmaf(E[1][3], b0, s1); s1 = fmaf(E[1][4], b1, s1); s1 = fmaf(E[1][5], b2, s1);
    s1 = fmaf(E[1][6], c0, s1); s1 = fmaf(E[1][7], c1, s1); s1 = fmaf(E[1][8], c2, s1);
    float s2 = E[2][0] * a0;
    s2 = fmaf(E[2][1], a1, s2); s2 = fmaf(E[2][2], a2, s2);
    s2 = fmaf(E[2][3], b0, s2); s2 = fmaf(E[2][4], b1, s2); s2 = fmaf(E[2][5], b2, s2);
    s2 = fmaf(E[2][6], c0, s2); s2 = fmaf(E[2][7], c1, s2); s2 = fmaf(E[2][8], c2, s2);

    float ndc = fmaf(fg, -EX2C, trg * -EX2C);   // (-fg - trg) * log2e, 2 fma-class ops
    if (DONORM) {
        float m = fmaxf(a0, a1); m = fmaxf(m, a2);
        m = fmaxf(m, b0); m = fmaxf(m, b1); m = fmaxf(m, b2);
        m = fmaxf(m, c0); m = fmaxf(m, c1); m = fmaxf(m, c2);
        float lm = __logf(m);
        kfold(lm, LS, LC);
        ndc = fmaf(-lm, EX2C, ndc);
    }
    a0 = ex2f(fmaf(f0, EX2C, ndc)) * s0;
    a1 = ex2f(fmaf(f1, EX2C, ndc)) * s1;
    a2 = ex2f(fmaf(f2, EX2C, ndc)) * s2;
    tagprev = tg;
}

__global__ void __launch_bounds__(THREADS, 1)
crf_nll_kernel(const float* __restrict__ feats,
               const int*   __restrict__ tags,
               const float* __restrict__ trans,
               float* __restrict__ out)
{
    __shared__ __align__(16) float s_feats[DEPTH][WARPS_PB][SEQ_PW][FSTRIDE]; // 44160 B
    __shared__ __align__(16) int   s_tags [DEPTH][WARPS_PB][SEQ_PW][CH];      //  3840 B
    __shared__ float s_trans[KTAGS * KTAGS];

    const int tid = threadIdx.x;
    if (tid < KTAGS * KTAGS) s_trans[tid] = trans[tid];
    __syncthreads();

    const int w    = tid >> 5;
    const int lane = tid & 31;
    int grp, k;
    if (lane < 30) { grp = lane / 3; k = lane - 3 * grp; }
    else           { grp = 0;        k = lane - 30;      }
    const int glane = 3 * grp;
    const int k1 = (k + 1) % 3, k2 = (k + 2) % 3;
    const int peer1 = glane + k1, peer2 = glane + k2;
    const int row0 = 3 * k;
    const int b = blockIdx.x * SEQ_PB + w * SEQ_PW + grp;
    const bool writer = (lane < 30) && (k == 0) && (b < BB);

    float E[3][9], SV[3], ES[3];
#pragma unroll
    for (int i = 0; i < 3; i++) {
        const float* tr = &s_trans[(row0 + i) * KTAGS];
#pragma unroll
        for (int q = 0; q < 3; q++) {
            E[i][q]     = __expf(tr[3 * k  + q]);
            E[i][3 + q] = __expf(tr[3 * k1 + q]);
            E[i][6 + q] = __expf(tr[3 * k2 + q]);
        }
        SV[i] = tr[START_TAG];
        ES[i] = __expf(s_trans[STOP_TAG * KTAGS + (row0 + i)]);
    }

    // ---- cp.async plan (proven): 240 16B units spread over all 32 lanes ----
    const char* srcp[8];
    uint32_t    dstp[8];
    int         sadv[8];
    int         dadv[8];
    bool        act [8];
#pragma unroll
    for (int r = 0; r < 8; r++) {
        int u = lane + 32 * r;
        act[r] = (u < 240);
        int uu = act[r] ? u : 0;
        int s  = uu / 24;
        int kk = uu % 24;
        int bs = blockIdx.x * SEQ_PB + w * SEQ_PW + s;
        if (bs >= BB) bs = BB - 1;
        if (kk < 22) {
            srcp[r] = (const char*)feats + (size_t)bs * TT * KTAGS * 4 + kk * 16;
            sadv[r] = CH * KTAGS * 4;
            dstp[r] = (uint32_t)__cvta_generic_to_shared(&s_feats[0][w][s][kk * 4]);
            dadv[r] = (int)sizeof(s_feats[0]);
        } else {
            srcp[r] = (const char*)tags + (size_t)bs * TT * 4 + (kk - 22) * 16;
            sadv[r] = CH * 4;
            dstp[r] = (uint32_t)__cvta_generic_to_shared(&s_tags[0][w][s][(kk - 22) * 4]);
            dadv[r] = (int)sizeof(s_tags[0]);
        }
    }

    auto issue_chunk = [&](int c) {
        int d = c & (DEPTH - 1);
#pragma unroll
        for (int r = 0; r < 8; r++) {
            if (act[r]) {
                uint32_t dd = dstp[r] + d * dadv[r];
                const char* ss = srcp[r] + (size_t)c * sadv[r];
                asm volatile("cp.async.ca.shared.global [%0], [%1], 16;" :: "r"(dd), "l"(ss));
            }
        }
        asm volatile("cp.async.commit_group;" ::: "memory");
    };

#pragma unroll
    for (int c = 0; c < DEPTH; c++) issue_chunk(c);

    float a0 = 0.f, a1 = 0.f, a2 = 0.f;
    float LS = 0.f, LC = 0.f;
    int   tagprev = START_TAG;

    // One 8-step slot; tags consumed directly from int4 components (no array).
    auto do8 = [&](int d, bool c0peel) {
        const float* sf = &s_feats[d][w][grp][0];
        const int4*  tq = (const int4*)&s_tags[d][w][grp][0];
        const int4 tA = tq[0], tB = tq[1];

        if (c0peel) {
            float f0 = sf[row0], f1 = sf[row0 + 1], f2 = sf[row0 + 2];
            int tg0 = tA.x;
            float fg  = sf[tg0];
            float tr0 = s_trans[tg0 * KTAGS + START_TAG];
            float ndc = fmaf(fg, -EX2C, tr0 * -EX2C);
            a0 = ex2f(fmaf(SV[0] + f0, EX2C, ndc));
            a1 = ex2f(fmaf(SV[1] + f1, EX2C, ndc));
            a2 = ex2f(fmaf(SV[2] + f2, EX2C, ndc));
            tagprev = tg0;
        } else {
            crf_step<true>(sf, 0, tA.x, s_trans, E, peer1, peer2, row0,
                           a0, a1, a2, LS, LC, tagprev);
        }
        crf_step<false>(sf, 1, tA.y, s_trans, E, peer1, peer2, row0, a0, a1, a2, LS, LC, tagprev);
        crf_step<false>(sf, 2, tA.z, s_trans, E, peer1, peer2, row0, a0, a1, a2, LS, LC, tagprev);
        crf_step<false>(sf, 3, tA.w, s_trans, E, peer1, peer2, row0, a0, a1, a2, LS, LC, tagprev);
        crf_step<false>(sf, 4, tB.x, s_trans, E, peer1, peer2, row0, a0, a1, a2, LS, LC, tagprev);
        crf_step<false>(sf, 5, tB.y, s_trans, E, peer1, peer2, row0, a0, a1, a2, LS, LC, tagprev);
        crf_step<false>(sf, 6, tB.z, s_trans, E, peer1, peer2, row0, a0, a1, a2, LS, LC, tagprev);
        crf_step<false>(sf, 7, tB.w, s_trans, E, peer1, peer2, row0, a0, a1, a2, LS, LC, tagprev);
    };

    // Paired-chunk loop: one wait + one sync pair per 16 steps.
    for (int c = 0; c < NCHK; c += 2) {
        asm volatile("cp.async.wait_group %0;" :: "n"(DEPTH - 2) : "memory");
        __syncwarp();

        do8(c & (DEPTH - 1), c == 0);
        do8((c + 1) & (DEPTH - 1), false);

        __syncwarp();
        if (c + DEPTH < NCHK) {
            issue_chunk(c + DEPTH);
            issue_chunk(c + DEPTH + 1);
        } else {
            asm volatile("cp.async.commit_group;" ::: "memory");
            asm volatile("cp.async.commit_group;" ::: "memory");
        }
    }

    // finalize: NLL = L + log( sum_p a_p * exp(trans[STOP,p]) ) - trans[STOP, tag_last]
    float term = a0 * ES[0];
    term = fmaf(a1, ES[1], term);
    term = fmaf(a2, ES[2], term);
    float fsum = term + __shfl_sync(0xffffffffu, term, peer1)
                      + __shfl_sync(0xffffffffu, term, peer2);

    float res = (LS - LC) + __logf(fsum) - s_trans[STOP_TAG * KTAGS + tagprev];

    if (writer) out[b] = res;
}

extern "C" void kernel_launch(void* const* d_in, const int* in_sizes, int n_in,
                              void* d_out, int out_size)
{
    const float* feats = (const float*)d_in[0];
    const int*   tags  = (const int*)d_in[1];
    const float* trans = (const float*)d_in[2];
    float* out = (float*)d_out;

    dim3 grid((BB + SEQ_PB - 1) / SEQ_PB);   // 137 blocks, single wave
    dim3 block(THREADS);                     // 96 threads = 3 warps = 30 sequences
    crf_nll_kernel<<<grid, block>>>(feats, tags, trans, out);
}

// round 16
// speedup vs baseline: 1.7152x; 1.0368x over previous
#include <cuda_runtime.h>
#include <cuda_bf16.h>
#include <cstdint>

#define KTAGS 11
#define TT    2048
#define BB    4096
#define CH    8              // steps per chunk
#define NCHK  (TT / CH)      // 256
#define DEPTH 4
#define WARPS_PB 3
#define SEQ_PW   10
#define SEQ_PB   (WARPS_PB * SEQ_PW)   // 30
#define THREADS  (WARPS_PB * 32)       // 96
#define FSTRIDE  92
#define START_TAG 10
#define STOP_TAG  9
#define EX2C 1.4426950408889634f   // log2(e)

__device__ __forceinline__ float ex2f(float x) {
    float r; asm("ex2.approx.f32 %0, %1;" : "=f"(r) : "f"(x)); return r;
}
__device__ __forceinline__ void kfold(float x, float& s, float& c) {
    float y = x - c;
    float t = s + y;
    c = (t - s) - y;
    s = t;
}

// One gold-shifted forward step. Single-chain dots, own states first.
template<bool DONORM>
__device__ __forceinline__ void crf_step(const float* __restrict__ sf, int tc, int tg,
                                         const float* __restrict__ s_trans,
                                         const float (&E)[3][9],
                                         int peer1, int peer2, int row0,
                                         float& a0, float& a1, float& a2,
                                         float& LS, float& LC, int& tagprev)
{
    const float* fr = &sf[tc * KTAGS + row0];
    float f0 = fr[0], f1 = fr[1], f2 = fr[2];
    float fg  = sf[tc * KTAGS + tg];              // group-uniform smem broadcast
    float trg = s_trans[tg * KTAGS + tagprev];    // group-uniform

    float b0 = __shfl_sync(0xffffffffu, a0, peer1);
    float b1 = __shfl_sync(0xffffffffu, a1, peer1);
    float b2 = __shfl_sync(0xffffffffu, a2, peer1);
    float c0 = __shfl_sync(0xffffffffu, a0, peer2);
    float c1 = __shfl_sync(0xffffffffu, a1, peer2);
    float c2 = __shfl_sync(0xffffffffu, a2, peer2);

    float s0 = E[0][0] * a0;
    s0 = fmaf(E[0][1], a1, s0); s0 = fmaf(E[0][2], a2, s0);
    s0 = fmaf(E[0][3], b0, s0); s0 = fmaf(E[0][4], b1, s0); s0 = fmaf(E[0][5], b2, s0);
    s0 = fmaf(E[0][6], c0, s0); s0 = fmaf(E[0][7], c1, s0); s0 = fmaf(E[0][8], c2, s0);
    float s1 = E[1][0] * a0;
    s1 = fmaf(E[1][1], a1, s1); s1 = fmaf(E[1][2], a2, s1);
    s1 = fmaf(E[1][3], b0, s1); s1 = fmaf(E[1][4], b1, s1); s1 = fmaf(E[1][5], b2, s1);
    s1 = fmaf(E[1][6], c0, s1); s1 = fmaf(E[1][7], c1, s1); s1 = fmaf(E[1][8], c2, s1);
    float s2 = E[2][0] * a0;
    s2 = fmaf(E[2][1], a1, s2); s2 = fmaf(E[2][2], a2, s2);
    s2 = fmaf(E[2][3], b0, s2); s2 = fmaf(E[2][4], b1, s2); s2 = fmaf(E[2][5], b2, s2);
    s2 = fmaf(E[2][6], c0, s2); s2 = fmaf(E[2][7], c1, s2); s2 = fmaf(E[2][8], c2, s2);

    float ndc = fmaf(fg, -EX2C, trg * -EX2C);   // (-fg - trg) * log2e
    if (DONORM) {
        float m = fmaxf(a0, a1); m = fmaxf(m, a2);
        m = fmaxf(m, b0); m = fmaxf(m, b1); m = fmaxf(m, b2);
        m = fmaxf(m, c0); m = fmaxf(m, c1); m = fmaxf(m, c2);
        float lm = __logf(m);
        kfold(lm, LS, LC);
        ndc = fmaf(-lm, EX2C, ndc);
    }
    a0 = ex2f(fmaf(f0, EX2C, ndc)) * s0;
    a1 = ex2f(fmaf(f1, EX2C, ndc)) * s1;
    a2 = ex2f(fmaf(f2, EX2C, ndc)) * s2;
    tagprev = tg;
}

__global__ void __launch_bounds__(THREADS, 1)
crf_nll_kernel(const float* __restrict__ feats,
               const int*   __restrict__ tags,
               const float* __restrict__ trans,
               float* __restrict__ out)
{
    __shared__ __align__(16) float s_feats[DEPTH][WARPS_PB][SEQ_PW][FSTRIDE]; // 44160 B
    __shared__ __align__(16) int   s_tags [DEPTH][WARPS_PB][SEQ_PW][CH];      //  3840 B
    __shared__ float s_trans[KTAGS * KTAGS];

    const int tid = threadIdx.x;
    if (tid < KTAGS * KTAGS) s_trans[tid] = trans[tid];
    __syncthreads();

    const int w    = tid >> 5;
    const int lane = tid & 31;
    int grp, k;
    if (lane < 30) { grp = lane / 3; k = lane - 3 * grp; }
    else           { grp = 0;        k = lane - 30;      }
    const int glane = 3 * grp;
    const int k1 = (k + 1) % 3, k2 = (k + 2) % 3;
    const int peer1 = glane + k1, peer2 = glane + k2;
    const int row0 = 3 * k;
    const int b = blockIdx.x * SEQ_PB + w * SEQ_PW + grp;
    const bool writer = (lane < 30) && (k == 0) && (b < BB);

    float E[3][9], SV[3], ES[3];
#pragma unroll
    for (int i = 0; i < 3; i++) {
        const float* tr = &s_trans[(row0 + i) * KTAGS];
#pragma unroll
        for (int q = 0; q < 3; q++) {
            E[i][q]     = __expf(tr[3 * k  + q]);
            E[i][3 + q] = __expf(tr[3 * k1 + q]);
            E[i][6 + q] = __expf(tr[3 * k2 + q]);
        }
        SV[i] = tr[START_TAG];
        ES[i] = __expf(s_trans[STOP_TAG * KTAGS + (row0 + i)]);
    }

    // ---- cp.async plan (proven): 240 16B units spread over all 32 lanes ----
    const char* srcp[8];
    uint32_t    dstp[8];
    int         sadv[8];
    int         dadv[8];
    bool        act [8];
#pragma unroll
    for (int r = 0; r < 8; r++) {
        int u = lane + 32 * r;
        act[r] = (u < 240);
        int uu = act[r] ? u : 0;
        int s  = uu / 24;
        int kk = uu % 24;
        int bs = blockIdx.x * SEQ_PB + w * SEQ_PW + s;
        if (bs >= BB) bs = BB - 1;
        if (kk < 22) {
            srcp[r] = (const char*)feats + (size_t)bs * TT * KTAGS * 4 + kk * 16;
            sadv[r] = CH * KTAGS * 4;
            dstp[r] = (uint32_t)__cvta_generic_to_shared(&s_feats[0][w][s][kk * 4]);
            dadv[r] = (int)sizeof(s_feats[0]);
        } else {
            srcp[r] = (const char*)tags + (size_t)bs * TT * 4 + (kk - 22) * 16;
            sadv[r] = CH * 4;
            dstp[r] = (uint32_t)__cvta_generic_to_shared(&s_tags[0][w][s][(kk - 22) * 4]);
            dadv[r] = (int)sizeof(s_tags[0]);
        }
    }

    auto issue_chunk = [&](int c) {
        int d = c & (DEPTH - 1);
#pragma unroll
        for (int r = 0; r < 8; r++) {
            if (act[r]) {
                uint32_t dd = dstp[r] + d * dadv[r];
                const char* ss = srcp[r] + (size_t)c * sadv[r];
                asm volatile("cp.async.ca.shared.global [%0], [%1], 16;" :: "r"(dd), "l"(ss));
            }
        }
        asm volatile("cp.async.commit_group;" ::: "memory");
    };

#pragma unroll
    for (int c = 0; c < DEPTH; c++) issue_chunk(c);

    float a0 = 0.f, a1 = 0.f, a2 = 0.f;
    float LS = 0.f, LC = 0.f;
    int   tagprev = START_TAG;

    // Steady-state 8-step slot (norm at t=0), branch-free.
    auto do8 = [&](int d) {
        const float* sf = &s_feats[d][w][grp][0];
        const int4*  tq = (const int4*)&s_tags[d][w][grp][0];
        const int4 tA = tq[0], tB = tq[1];
        crf_step<true >(sf, 0, tA.x, s_trans, E, peer1, peer2, row0, a0, a1, a2, LS, LC, tagprev);
        crf_step<false>(sf, 1, tA.y, s_trans, E, peer1, peer2, row0, a0, a1, a2, LS, LC, tagprev);
        crf_step<false>(sf, 2, tA.z, s_trans, E, peer1, peer2, row0, a0, a1, a2, LS, LC, tagprev);
        crf_step<false>(sf, 3, tA.w, s_trans, E, peer1, peer2, row0, a0, a1, a2, LS, LC, tagprev);
        crf_step<false>(sf, 4, tB.x, s_trans, E, peer1, peer2, row0, a0, a1, a2, LS, LC, tagprev);
        crf_step<false>(sf, 5, tB.y, s_trans, E, peer1, peer2, row0, a0, a1, a2, LS, LC, tagprev);
        crf_step<false>(sf, 6, tB.z, s_trans, E, peer1, peer2, row0, a0, a1, a2, LS, LC, tagprev);
        crf_step<false>(sf, 7, tB.w, s_trans, E, peer1, peer2, row0, a0, a1, a2, LS, LC, tagprev);
    };

    // ---- peeled prologue: chunk pair (0, 1) ----
    {
        asm volatile("cp.async.wait_group %0;" :: "n"(DEPTH - 2) : "memory");
        __syncwarp();

        // chunk 0: t=0 init (prev=START only), then steps 1..7
        {
            const float* sf = &s_feats[0][w][grp][0];
            const int4*  tq = (const int4*)&s_tags[0][w][grp][0];
            const int4 tA = tq[0], tB = tq[1];
            float f0 = sf[row0], f1 = sf[row0 + 1], f2 = sf[row0 + 2];
            int tg0 = tA.x;
            float fg  = sf[tg0];
            float tr0 = s_trans[tg0 * KTAGS + START_TAG];
            float ndc = fmaf(fg, -EX2C, tr0 * -EX2C);
            a0 = ex2f(fmaf(SV[0] + f0, EX2C, ndc));
            a1 = ex2f(fmaf(SV[1] + f1, EX2C, ndc));
            a2 = ex2f(fmaf(SV[2] + f2, EX2C, ndc));
            tagprev = tg0;
            crf_step<false>(sf, 1, tA.y, s_trans, E, peer1, peer2, row0, a0, a1, a2, LS, LC, tagprev);
            crf_step<false>(sf, 2, tA.z, s_trans, E, peer1, peer2, row0, a0, a1, a2, LS, LC, tagprev);
            crf_step<false>(sf, 3, tA.w, s_trans, E, peer1, peer2, row0, a0, a1, a2, LS, LC, tagprev);
            crf_step<false>(sf, 4, tB.x, s_trans, E, peer1, peer2, row0, a0, a1, a2, LS, LC, tagprev);
            crf_step<false>(sf, 5, tB.y, s_trans, E, peer1, peer2, row0, a0, a1, a2, LS, LC, tagprev);
            crf_step<false>(sf, 6, tB.z, s_trans, E, peer1, peer2, row0, a0, a1, a2, LS, LC, tagprev);
            crf_step<false>(sf, 7, tB.w, s_trans, E, peer1, peer2, row0, a0, a1, a2, LS, LC, tagprev);
        }
        do8(1);

        __syncwarp();
        issue_chunk(DEPTH);
        issue_chunk(DEPTH + 1);
    }

    // ---- branch-minimal main loop over chunk pairs (2,3), (4,5), ... ----
    for (int c = 2; c < NCHK; c += 2) {
        asm volatile("cp.async.wait_group %0;" :: "n"(DEPTH - 2) : "memory");
        __syncwarp();

        do8(c & (DEPTH - 1));
        do8((c + 1) & (DEPTH - 1));

        __syncwarp();
        if (c + DEPTH < NCHK) {
            issue_chunk(c + DEPTH);
            issue_chunk(c + DEPTH + 1);
        } else {
            asm volatile("cp.async.commit_group;" ::: "memory");
            asm volatile("cp.async.commit_group;" ::: "memory");
        }
    }

    // finalize: NLL = L + log( sum_p a_p * exp(trans[STOP,p]) ) - trans[STOP, tag_last]
    float term = a0 * ES[0];
    term = fmaf(a1, ES[1], term);
    term = fmaf(a2, ES[2], term);
    float fsum = term + __shfl_sync(0xffffffffu, term, peer1)
                      + __shfl_sync(0xffffffffu, term, peer2);

    float res = (LS - LC) + __logf(fsum) - s_trans[STOP_TAG * KTAGS + tagprev];

    if (writer) out[b] = res;
}

extern "C" void kernel_launch(void* const* d_in, const int* in_sizes, int n_in,
                              void* d_out, int out_size)
{
    const float* feats = (const float*)d_in[0];
    const int*   tags  = (const int*)d_in[1];
    const float* trans = (const float*)d_in[2];
    float* out = (float*)d_out;

    dim3 grid((BB + SEQ_PB - 1) / SEQ_PB);   // 137 blocks, single wave
    dim3 block(THREADS);                     // 96 threads = 3 warps = 30 sequences
    crf_nll_kernel<<<grid, block>>>(feats, tags, trans, out);
}

// round 17
// speedup vs baseline: 1.7706x; 1.0323x over previous
#include <cuda_runtime.h>
#include <cuda_bf16.h>
#include <cstdint>

#define KTAGS 11
#define TT    2048
#define BB    4096
#define CH    8              // steps per chunk
#define NCHK  (TT / CH)      // 256
#define DEPTH 4
#define WARPS_PB 3
#define SEQ_PW   10
#define SEQ_PB   (WARPS_PB * SEQ_PW)   // 30
#define THREADS  (WARPS_PB * 32)       // 96
#define FSTRIDE  92
#define START_TAG 10
#define STOP_TAG  9
#define EX2C 1.4426950408889634f   // log2(e)

__device__ __forceinline__ float ex2f(float x) {
    float r; asm("ex2.approx.f32 %0, %1;" : "=f"(r) : "f"(x)); return r;
}

// One gold-shifted forward step. Single-chain dots, own states first.
// NORM scale = group-base lane's a0 (group-uniform via the shuffled values).
template<bool DONORM>
__device__ __forceinline__ void crf_step(const float* __restrict__ sf, int tc, int tg,
                                         const float* __restrict__ s_transC,
                                         const float (&E)[3][9],
                                         int peer1, int peer2, int row0,
                                         bool isk0, bool isk1,
                                         float& a0, float& a1, float& a2,
                                         float& LS, int& tagprev)
{
    const float* fr = &sf[tc * KTAGS + row0];
    float f0 = fr[0], f1 = fr[1], f2 = fr[2];
    float fg   = sf[tc * KTAGS + tg];               // group-uniform smem broadcast
    float trgC = s_transC[tg * KTAGS + tagprev];    // pre-scaled by -log2e

    float b0 = __shfl_sync(0xffffffffu, a0, peer1);
    float b1 = __shfl_sync(0xffffffffu, a1, peer1);
    float b2 = __shfl_sync(0xffffffffu, a2, peer1);
    float c0 = __shfl_sync(0xffffffffu, a0, peer2);
    float c1 = __shfl_sync(0xffffffffu, a1, peer2);
    float c2 = __shfl_sync(0xffffffffu, a2, peer2);

    float s0 = E[0][0] * a0;
    s0 = fmaf(E[0][1], a1, s0); s0 = fmaf(E[0][2], a2, s0);
    s0 = fmaf(E[0][3], b0, s0); s0 = fmaf(E[0][4], b1, s0); s0 = fmaf(E[0][5], b2, s0);
    s0 = fmaf(E[0][6], c0, s0); s0 = fmaf(E[0][7], c1, s0); s0 = fmaf(E[0][8], c2, s0);
    float s1 = E[1][0] * a0;
    s1 = fmaf(E[1][1], a1, s1); s1 = fmaf(E[1][2], a2, s1);
    s1 = fmaf(E[1][3], b0, s1); s1 = fmaf(E[1][4], b1, s1); s1 = fmaf(E[1][5], b2, s1);
    s1 = fmaf(E[1][6], c0, s1); s1 = fmaf(E[1][7], c1, s1); s1 = fmaf(E[1][8], c2, s1);
    float s2 = E[2][0] * a0;
    s2 = fmaf(E[2][1], a1, s2); s2 = fmaf(E[2][2], a2, s2);
    s2 = fmaf(E[2][3], b0, s2); s2 = fmaf(E[2][4], b1, s2); s2 = fmaf(E[2][5], b2, s2);
    s2 = fmaf(E[2][6], c0, s2); s2 = fmaf(E[2][7], c1, s2); s2 = fmaf(E[2][8], c2, s2);

    float ndc = fmaf(fg, -EX2C, trgC);
    if (DONORM) {
        // group-uniform scale: the base lane's a0 (positive, within e^11 of max)
        float m = isk0 ? a0 : (isk1 ? c0 : b0);
        float lm = __logf(m);
        LS += lm;
        ndc = fmaf(-lm, EX2C, ndc);
    }
    a0 = ex2f(fmaf(f0, EX2C, ndc)) * s0;
    a1 = ex2f(fmaf(f1, EX2C, ndc)) * s1;
    a2 = ex2f(fmaf(f2, EX2C, ndc)) * s2;
    tagprev = tg;
}

__global__ void __launch_bounds__(THREADS, 1)
crf_nll_kernel(const float* __restrict__ feats,
               const int*   __restrict__ tags,
               const float* __restrict__ trans,
               float* __restrict__ out)
{
    __shared__ __align__(16) float s_feats[DEPTH][WARPS_PB][SEQ_PW][FSTRIDE]; // 44160 B
    __shared__ __align__(16) int   s_tags [DEPTH][WARPS_PB][SEQ_PW][CH];      //  3840 B
    __shared__ float s_trans [KTAGS * KTAGS];
    __shared__ float s_transC[KTAGS * KTAGS];   // trans * (-log2e)

    const int tid = threadIdx.x;
    if (tid < KTAGS * KTAGS) {
        float v = trans[tid];
        s_trans [tid] = v;
        s_transC[tid] = v * (-EX2C);
    }
    __syncthreads();

    const int w    = tid >> 5;
    const int lane = tid & 31;
    int grp, k;
    if (lane < 30) { grp = lane / 3; k = lane - 3 * grp; }
    else           { grp = 0;        k = lane - 30;      }
    const int glane = 3 * grp;
    const int k1 = (k + 1) % 3, k2 = (k + 2) % 3;
    const int peer1 = glane + k1, peer2 = glane + k2;
    const int row0 = 3 * k;
    const bool isk0 = (k == 0), isk1 = (k == 1);
    const int b = blockIdx.x * SEQ_PB + w * SEQ_PW + grp;
    const bool writer = (lane < 30) && isk0 && (b < BB);

    float E[3][9], SV[3], ES[3];
#pragma unroll
    for (int i = 0; i < 3; i++) {
        const float* tr = &s_trans[(row0 + i) * KTAGS];
#pragma unroll
        for (int q = 0; q < 3; q++) {
            E[i][q]     = __expf(tr[3 * k  + q]);
            E[i][3 + q] = __expf(tr[3 * k1 + q]);
            E[i][6 + q] = __expf(tr[3 * k2 + q]);
        }
        SV[i] = tr[START_TAG];
        ES[i] = __expf(s_trans[STOP_TAG * KTAGS + (row0 + i)]);
    }

    // ---- cp.async plan (proven): 240 16B units spread over all 32 lanes ----
    const char* srcp[8];
    uint32_t    dstp[8];
    int         sadv[8];
    int         dadv[8];
    bool        act [8];
#pragma unroll
    for (int r = 0; r < 8; r++) {
        int u = lane + 32 * r;
        act[r] = (u < 240);
        int uu = act[r] ? u : 0;
        int s  = uu / 24;
        int kk = uu % 24;
        int bs = blockIdx.x * SEQ_PB + w * SEQ_PW + s;
        if (bs >= BB) bs = BB - 1;
        if (kk < 22) {
            srcp[r] = (const char*)feats + (size_t)bs * TT * KTAGS * 4 + kk * 16;
            sadv[r] = CH * KTAGS * 4;
            dstp[r] = (uint32_t)__cvta_generic_to_shared(&s_feats[0][w][s][kk * 4]);
            dadv[r] = (int)sizeof(s_feats[0]);
        } else {
            srcp[r] = (const char*)tags + (size_t)bs * TT * 4 + (kk - 22) * 16;
            sadv[r] = CH * 4;
            dstp[r] = (uint32_t)__cvta_generic_to_shared(&s_tags[0][w][s][(kk - 22) * 4]);
            dadv[r] = (int)sizeof(s_tags[0]);
        }
    }

    auto issue_chunk = [&](int c) {
        int d = c & (DEPTH - 1);
#pragma unroll
        for (int r = 0; r < 8; r++) {
            if (act[r]) {
                uint32_t dd = dstp[r] + d * dadv[r];
                const char* ss = srcp[r] + (size_t)c * sadv[r];
                asm volatile("cp.async.ca.shared.global [%0], [%1], 16;" :: "r"(dd), "l"(ss));
            }
        }
        asm volatile("cp.async.commit_group;" ::: "memory");
    };

#pragma unroll
    for (int c = 0; c < DEPTH; c++) issue_chunk(c);

    float a0 = 0.f, a1 = 0.f, a2 = 0.f;
    float LS = 0.f;
    int   tagprev = START_TAG;

    // Steady-state 8-step slot (norm at t=0), branch-free.
    auto do8 = [&](int d) {
        const float* sf = &s_feats[d][w][grp][0];
        const int4*  tq = (const int4*)&s_tags[d][w][grp][0];
        const int4 tA = tq[0], tB = tq[1];
        crf_step<true >(sf, 0, tA.x, s_transC, E, peer1, peer2, row0, isk0, isk1, a0, a1, a2, LS, tagprev);
        crf_step<false>(sf, 1, tA.y, s_transC, E, peer1, peer2, row0, isk0, isk1, a0, a1, a2, LS, tagprev);
        crf_step<false>(sf, 2, tA.z, s_transC, E, peer1, peer2, row0, isk0, isk1, a0, a1, a2, LS, tagprev);
        crf_step<false>(sf, 3, tA.w, s_transC, E, peer1, peer2, row0, isk0, isk1, a0, a1, a2, LS, tagprev);
        crf_step<false>(sf, 4, tB.x, s_transC, E, peer1, peer2, row0, isk0, isk1, a0, a1, a2, LS, tagprev);
        crf_step<false>(sf, 5, tB.y, s_transC, E, peer1, peer2, row0, isk0, isk1, a0, a1, a2, LS, tagprev);
        crf_step<false>(sf, 6, tB.z, s_transC, E, peer1, peer2, row0, isk0, isk1, a0, a1, a2, LS, tagprev);
        crf_step<false>(sf, 7, tB.w, s_transC, E, peer1, peer2, row0, isk0, isk1, a0, a1, a2, LS, tagprev);
    };

    // ---- peeled prologue: chunk pair (0, 1) ----
    {
        asm volatile("cp.async.wait_group %0;" :: "n"(DEPTH - 2) : "memory");
        __syncwarp();

        // chunk 0: t=0 init (prev=START only), then steps 1..7
        {
            const float* sf = &s_feats[0][w][grp][0];
            const int4*  tq = (const int4*)&s_tags[0][w][grp][0];
            const int4 tA = tq[0], tB = tq[1];
            float f0 = sf[row0], f1 = sf[row0 + 1], f2 = sf[row0 + 2];
            int tg0 = tA.x;
            float fg = sf[tg0];
            float ndc = fmaf(fg, -EX2C, s_transC[tg0 * KTAGS + START_TAG]);
            a0 = ex2f(fmaf(SV[0] + f0, EX2C, ndc));
            a1 = ex2f(fmaf(SV[1] + f1, EX2C, ndc));
            a2 = ex2f(fmaf(SV[2] + f2, EX2C, ndc));
            tagprev = tg0;
            crf_step<false>(sf, 1, tA.y, s_transC, E, peer1, peer2, row0, isk0, isk1, a0, a1, a2, LS, tagprev);
            crf_step<false>(sf, 2, tA.z, s_transC, E, peer1, peer2, row0, isk0, isk1, a0, a1, a2, LS, tagprev);
            crf_step<false>(sf, 3, tA.w, s_transC, E, peer1, peer2, row0, isk0, isk1, a0, a1, a2, LS, tagprev);
            crf_step<false>(sf, 4, tB.x, s_transC, E, peer1, peer2, row0, isk0, isk1, a0, a1, a2, LS, tagprev);
            crf_step<false>(sf, 5, tB.y, s_transC, E, peer1, peer2, row0, isk0, isk1, a0, a1, a2, LS, tagprev);
            crf_step<false>(sf, 6, tB.z, s_transC, E, peer1, peer2, row0, isk0, isk1, a0, a1, a2, LS, tagprev);
            crf_step<false>(sf, 7, tB.w, s_transC, E, peer1, peer2, row0, isk0, isk1, a0, a1, a2, LS, tagprev);
        }
        do8(1);

        __syncwarp();
        issue_chunk(DEPTH);
        issue_chunk(DEPTH + 1);
    }

    // ---- branch-minimal main loop over chunk pairs (2,3), (4,5), ... ----
    for (int c = 2; c < NCHK; c += 2) {
        asm volatile("cp.async.wait_group %0;" :: "n"(DEPTH - 2) : "memory");
        __syncwarp();

        do8(c & (DEPTH - 1));
        do8((c + 1) & (DEPTH - 1));

        __syncwarp();
        if (c + DEPTH < NCHK) {
            issue_chunk(c + DEPTH);
            issue_chunk(c + DEPTH + 1);
        } else {
            asm volatile("cp.async.commit_group;" ::: "memory");
            asm volatile("cp.async.commit_group;" ::: "memory");
        }
    }

    // finalize: NLL = L + log( sum_p a_p * exp(trans[STOP,p]) ) - trans[STOP, tag_last]
    float term = a0 * ES[0];
    term = fmaf(a1, ES[1], term);
    term = fmaf(a2, ES[2], term);
    float fsum = term + __shfl_sync(0xffffffffu, term, peer1)
                      + __shfl_sync(0xffffffffu, term, peer2);

    float res = LS + __logf(fsum) - s_trans[STOP_TAG * KTAGS + tagprev];

    if (writer) out[b] = res;
}

extern "C" void kernel_launch(void* const* d_in, const int* in_sizes, int n_in,
                              void* d_out, int out_size)
{
    const float* feats = (const float*)d_in[0];
    const int*   tags  = (const int*)d_in[1];
    const float* trans = (const float*)d_in[2];
    float* out = (float*)d_out;

    dim3 grid((BB + SEQ_PB - 1) / SEQ_PB);   // 137 blocks, single wave
    dim3 block(THREADS);                     // 96 threads = 3 warps = 30 sequences
    crf_nll_kernel<<<grid, block>>>(feats, tags, trans, out);
}